// round 12
// baseline (speedup 1.0000x reference)
#include <cuda_runtime.h>
#include <math.h>
#include <stdint.h>

#define NLY 6
#define DM 256
#define FFD 1024
#define VC 1024
#define SL 48
#define BSZ 64
#define NH 8
#define DHD 32
#define LT 49
#define ROWS_E (BSZ*SL)
#define NB 148
#define NT 256

// ---------------- device scratch ----------------
__device__ __align__(16) float g_pe[LT*DM];
__device__ unsigned g_keys[2*SL];
__device__ __align__(16) float g_X[ROWS_E*DM];
__device__ __align__(16) float g_T1[ROWS_E*FFD];
__device__ __align__(16) float g_T2[ROWS_E*DM];
__device__ __align__(16) float g_T3[ROWS_E*DM];
__device__ __align__(16) float g_mem[ROWS_E*DM];
__device__ __align__(16) float g_cK[NLY*ROWS_E*DM];
__device__ __align__(16) float g_cV[NLY*ROWS_E*DM];
__device__ __align__(16) float g_sK[NLY*BSZ*LT*DM];
__device__ __align__(16) float g_sV[NLY*BSZ*LT*DM];
__device__ __align__(16) float g_dx[BSZ*DM];
__device__ __align__(16) float g_dt[BSZ*FFD];
__device__ __align__(16) float g_dt2[BSZ*DM];
__device__ int g_choice[SL*BSZ];
__device__ unsigned g_barcnt = 0;
__device__ unsigned g_bargen = 0;

struct Prm {
  const int *xc, *xcat;
  const float *sos, *emb, *hw, *hb;
  const float *ewqkv, *ebqkv, *ewo, *ebo, *ew1, *eb1, *ew2, *eb2, *elnw, *elnb;
  const float *swqkv, *sbqkv, *swo, *sbo;
  const float *cwqkv, *cbqkv, *cwo, *cbo;
  const float *dw1, *db1, *dw2, *db2, *dlnw, *dlnb, *lnfw, *lnfb;
  float* out;
};

// ---------------- grid barrier (148 co-resident blocks) ----------------
__device__ __forceinline__ void gridbar() {
  __threadfence();               // drain my writes to device scope
  __syncthreads();
  if (threadIdx.x == 0) {
    unsigned gen = *(volatile unsigned*)&g_bargen;
    if (atomicAdd(&g_barcnt, 1u) == NB - 1u) {
      g_barcnt = 0u;
      __threadfence();
      atomicAdd(&g_bargen, 1u);
    } else {
      while (*(volatile unsigned*)&g_bargen == gen) __nanosleep(64);
    }
  }
  __syncthreads();
  __threadfence();               // gpu-scope fence => CCTL.IVALL: invalidate stale L1
}

// ---------------- Threefry-2x32, 20 rounds ----------------
__device__ __forceinline__ uint2 tf2x32(unsigned k0, unsigned k1,
                                        unsigned x0, unsigned x1) {
  unsigned ks2 = k0 ^ k1 ^ 0x1BD11BDAu;
  x0 += k0; x1 += k1;
#define TFR(r) { x0 += x1; x1 = (x1 << (r)) | (x1 >> (32 - (r))); x1 ^= x0; }
  TFR(13) TFR(15) TFR(26) TFR(6)   x0 += k1;  x1 += ks2 + 1u;
  TFR(17) TFR(29) TFR(16) TFR(24)  x0 += ks2; x1 += k0 + 2u;
  TFR(13) TFR(15) TFR(26) TFR(6)   x0 += k0;  x1 += k1 + 3u;
  TFR(17) TFR(29) TFR(16) TFR(24)  x0 += k1;  x1 += ks2 + 4u;
  TFR(13) TFR(15) TFR(26) TFR(6)   x0 += ks2; x1 += k0 + 5u;
#undef TFR
  return make_uint2(x0, x1);
}

__device__ __forceinline__ float pef(int l, int d) {
  const float c = (float)(-9.210340371976184 / 256.0);
  float dv = expf((float)(2 * (d >> 1)) * c);
  float ang = (float)l * dv;
  return (d & 1) ? cosf(ang) : sinf(ang);
}

// dot of length 4*n4 (a may be smem/global; w global, float4-aligned)
__device__ __forceinline__ float dotk(const float* a, const float* w, int n4) {
  float s = 0.f;
  const float4* a4 = (const float4*)a;
  const float4* w4 = (const float4*)w;
#pragma unroll 4
  for (int i = 0; i < n4; i++) {
    float4 x = a4[i]; float4 y = __ldg(w4 + i);
    s = fmaf(x.x, y.x, s); s = fmaf(x.y, y.y, s);
    s = fmaf(x.z, y.z, s); s = fmaf(x.w, y.w, s);
  }
  return s;
}

// block-wide sum (256 threads), red: 8 floats of smem
__device__ __forceinline__ float blksum(float v, float* red) {
  int lane = threadIdx.x & 31, wp = threadIdx.x >> 5;
#pragma unroll
  for (int o = 16; o; o >>= 1) v += __shfl_xor_sync(0xffffffffu, v, o);
  if (lane == 0) red[wp] = v;
  __syncthreads();
  float t = 0.f;
#pragma unroll
  for (int i = 0; i < 8; i++) t += red[i];
  __syncthreads();
  return t;
}

// 64x64 output tile of C = A(M,K)@B(N,K)^T + bias (+resid)(+relu)
__device__ __noinline__ void gtile(const float* A, const float* B,
                                   const float* bias, const float* resid,
                                   float* C, int N, int K, int relu,
                                   int bx, int by, float* SM) {
  float* As = SM;             // [16][68]
  float* Bs = SM + 16 * 68;   // [16][68]
  int t = threadIdx.x, tx = t & 15, ty = t >> 4;
  float acc[4][4] = {};
  const float* Ab = A + (size_t)(by * 64) * K;
  const float* Bb = B + (size_t)(bx * 64) * K;
  int lrow = t >> 2, lcol = (t & 3) * 4;
  for (int k0 = 0; k0 < K; k0 += 16) {
    float4 va = *(const float4*)(Ab + (size_t)lrow * K + k0 + lcol);
    As[(lcol + 0) * 68 + lrow] = va.x; As[(lcol + 1) * 68 + lrow] = va.y;
    As[(lcol + 2) * 68 + lrow] = va.z; As[(lcol + 3) * 68 + lrow] = va.w;
    float4 vb = *(const float4*)(Bb + (size_t)lrow * K + k0 + lcol);
    Bs[(lcol + 0) * 68 + lrow] = vb.x; Bs[(lcol + 1) * 68 + lrow] = vb.y;
    Bs[(lcol + 2) * 68 + lrow] = vb.z; Bs[(lcol + 3) * 68 + lrow] = vb.w;
    __syncthreads();
#pragma unroll
    for (int kk = 0; kk < 16; kk++) {
      float a[4], bb[4];
#pragma unroll
      for (int i = 0; i < 4; i++) a[i] = As[kk * 68 + ty * 4 + i];
#pragma unroll
      for (int j = 0; j < 4; j++) bb[j] = Bs[kk * 68 + tx * 4 + j];
#pragma unroll
      for (int i = 0; i < 4; i++)
#pragma unroll
        for (int j = 0; j < 4; j++) acc[i][j] = fmaf(a[i], bb[j], acc[i][j]);
    }
    __syncthreads();
  }
#pragma unroll
  for (int i = 0; i < 4; i++) {
    int m = by * 64 + ty * 4 + i;
#pragma unroll
    for (int j = 0; j < 4; j++) {
      int n = bx * 64 + tx * 4 + j;
      float v = acc[i][j];
      if (bias)  v += __ldg(bias + n);
      if (resid) v += resid[(size_t)m * N + n];
      if (relu)  v = fmaxf(v, 0.f);
      C[(size_t)m * N + n] = v;
    }
  }
  __syncthreads();
}

// encoder self-attn for one (head h, batch b); 256 threads
__device__ __noinline__ void enc_attn_unit(const float* QKV, float* O,
                                           int h, int b, float* SM) {
  float* Qs = SM;            // [48][32]
  float* Ks = SM + 1536;
  float* Vs = SM + 3072;
  float* pr = SM + 4608;     // [8][48]
  int t = threadIdx.x;
  for (int e = t; e < SL * DHD; e += NT) {
    int j = e >> 5, d = e & 31;
    const float* base = QKV + (size_t)(b * SL + j) * 768 + h * DHD + d;
    Qs[e] = base[0]; Ks[e] = base[256]; Vs[e] = base[512];
  }
  __syncthreads();
  int w = t >> 5, lane = t & 31;
  const float scale = 0.17677669529663687f;
  for (int q = w; q < SL; q += 8) {
    float s0 = 0.f, s1 = -1e30f;
#pragma unroll
    for (int d = 0; d < DHD; d++) s0 += Qs[q * 32 + d] * Ks[lane * 32 + d];
    s0 *= scale;
    if (lane < SL - 32) {
      float a = 0.f;
#pragma unroll
      for (int d = 0; d < DHD; d++) a += Qs[q * 32 + d] * Ks[(lane + 32) * 32 + d];
      s1 = a * scale;
    }
    float mx = fmaxf(s0, s1);
#pragma unroll
    for (int o = 16; o; o >>= 1) mx = fmaxf(mx, __shfl_xor_sync(~0u, mx, o));
    float e0 = expf(s0 - mx);
    float e1 = (lane < SL - 32) ? expf(s1 - mx) : 0.f;
    float sum = e0 + e1;
#pragma unroll
    for (int o = 16; o; o >>= 1) sum += __shfl_xor_sync(~0u, sum, o);
    float inv = 1.f / sum;
    pr[w * SL + lane] = e0 * inv;
    if (lane < SL - 32) pr[w * SL + lane + 32] = e1 * inv;
    __syncwarp();
    float acc = 0.f;
#pragma unroll 8
    for (int j = 0; j < SL; j++) acc += pr[w * SL + j] * Vs[j * 32 + lane];
    O[(size_t)(b * SL + q) * DM + h * DHD + lane] = acc;
    __syncwarp();
  }
  __syncthreads();
}

// LN over rows of width 256, rows distributed over grid
__device__ __forceinline__ void ln_rows(const float* x, const float* w,
                                        const float* b, float* out, int M,
                                        float* red) {
  int t = threadIdx.x;
  for (int r = blockIdx.x; r < M; r += NB) {
    float v = x[(size_t)r * DM + t];
    float mean = blksum(v, red) * (1.f / 256.f);
    float dd = v - mean;
    float var = blksum(dd * dd, red) * (1.f / 256.f);
    out[(size_t)r * DM + t] = dd * rsqrtf(var + 1e-5f) * w[t] + b[t];
  }
}

// ---------------- the megakernel ----------------
__global__ __launch_bounds__(NT, 1) void mega(Prm p) {
  __shared__ __align__(16) float SM[5248];
  const int bid = blockIdx.x, tid = threadIdx.x;
  const int gtid = bid * NT + tid;
  const int GT = NB * NT;
  const float scale = 0.17677669529663687f;

  // ---- P0: pe, step keys, decoder DX(step0), encoder embed ----
  for (int e = gtid; e < LT * DM; e += GT) g_pe[e] = pef(e >> 8, e & 255);
  if (gtid < SL) {
    uint2 r = tf2x32(0u, 42u, 0u, (unsigned)gtid);
    g_keys[2 * gtid] = r.x; g_keys[2 * gtid + 1] = r.y;
  }
  for (int e = gtid; e < BSZ * DM; e += GT)
    g_dx[e] = p.sos[e & 255] + pef(0, e & 255);
  for (int e = gtid; e < ROWS_E * DM; e += GT) {
    int r = e >> 8, d = e & 255, b = r / SL, s = r % SL;
    int tok = (s < 32) ? p.xc[b * 32 + s] : p.xcat[b * 16 + (s - 32)];
    g_X[e] = p.emb[((size_t)s * VC + tok) * DM + d] + pef(s, d);
  }
  gridbar();

  // ---- encoder ----
  for (int l = 0; l < NLY; l++) {
    for (int t = bid; t < 576; t += NB)
      gtile(g_X, p.ewqkv + (size_t)l * 196608, p.ebqkv + l * 768, nullptr,
            g_T1, 768, 256, 0, t % 12, t / 12, SM);
    gridbar();
    for (int u = bid; u < NH * BSZ; u += NB)
      enc_attn_unit(g_T1, g_T2, u & 7, u >> 3, SM);
    gridbar();
    for (int t = bid; t < 192; t += NB)
      gtile(g_T2, p.ewo + (size_t)l * 65536, p.ebo + l * 256, g_X,
            g_T3, 256, 256, 0, t % 4, t / 4, SM);
    gridbar();
    ln_rows(g_T3, p.elnw + l * 512, p.elnb + l * 512, g_X, ROWS_E, SM);
    gridbar();
    for (int t = bid; t < 768; t += NB)
      gtile(g_X, p.ew1 + (size_t)l * 262144, p.eb1 + l * 1024, nullptr,
            g_T1, 1024, 256, 1, t % 16, t / 16, SM);
    gridbar();
    for (int t = bid; t < 192; t += NB)
      gtile(g_T1, p.ew2 + (size_t)l * 262144, p.eb2 + l * 256, g_X,
            g_T2, 256, 1024, 0, t % 4, t / 4, SM);
    gridbar();
    ln_rows(g_T2, p.elnw + l * 512 + 256, p.elnb + l * 512 + 256, g_X, ROWS_E, SM);
    gridbar();
  }
  ln_rows(g_X, p.lnfw, p.lnfb, g_mem, ROWS_E, SM);
  gridbar();

  // ---- cross-attn K/V precompute: 6 layers x {K,V} x 192 tiles ----
  for (int t = bid; t < 2304; t += NB) {
    int l = t / 384, r = t % 384, kv = r / 192, tile = r % 192;
    const float* B = p.cwqkv + (size_t)l * 196608 + (size_t)(256 + kv * 256) * 256;
    const float* bias = p.cbqkv + l * 768 + 256 + kv * 256;
    float* C = (kv ? g_cV : g_cK) + (size_t)l * ROWS_E * DM;
    gtile(g_mem, B, bias, nullptr, C, 256, 256, 0, tile % 4, tile / 4, SM);
  }
  gridbar();

  // ---- autoregressive decode ----
  for (int step = 0; step < SL; step++) {
    for (int l = 0; l < NLY; l++) {
      // A: qkv GEMV -> g_dt[64x768]
      for (int e = gtid; e < BSZ * 768; e += GT) {
        int m = e / 768, n = e - m * 768;
        g_dt[e] = __ldg(p.sbqkv + l * 768 + n) +
                  dotk(g_dx + m * DM, p.swqkv + (size_t)l * 196608 + (size_t)n * 256, 64);
      }
      gridbar();
      // B: self-attn + out-proj + resid + LN  (block per batch row)
      if (bid < BSZ) {
        int b = bid;
        float* q = SM;            // 256
        float* o = SM + 256;      // 256
        float* pr = SM + 512;     // 8*49
        float* red = SM + 912;
        const float* qkv = g_dt + b * 768;
        float* Kc = g_sK + (size_t)(l * BSZ + b) * LT * DM;
        float* Vc = g_sV + (size_t)(l * BSZ + b) * LT * DM;
        Kc[step * DM + tid] = qkv[256 + tid];
        Vc[step * DM + tid] = qkv[512 + tid];
        q[tid] = qkv[tid];
        __threadfence_block();
        __syncthreads();
        int h = tid >> 5, lane = tid & 31;
        const float* Kb = Kc + h * DHD;
        const float* Vb = Vc + h * DHD;
        float s0 = -1e30f, s1 = -1e30f;
        if (lane <= step) {
          float a = 0.f;
#pragma unroll
          for (int d = 0; d < DHD; d++) a += q[h * 32 + d] * Kb[lane * DM + d];
          s0 = a * scale;
        }
        if (lane + 32 <= step) {
          float a = 0.f;
#pragma unroll
          for (int d = 0; d < DHD; d++) a += q[h * 32 + d] * Kb[(lane + 32) * DM + d];
          s1 = a * scale;
        }
        float mx = fmaxf(s0, s1);
#pragma unroll
        for (int o2 = 16; o2; o2 >>= 1) mx = fmaxf(mx, __shfl_xor_sync(~0u, mx, o2));
        float e0 = (lane <= step) ? expf(s0 - mx) : 0.f;
        float e1 = (lane + 32 <= step) ? expf(s1 - mx) : 0.f;
        float sum = e0 + e1;
#pragma unroll
        for (int o2 = 16; o2; o2 >>= 1) sum += __shfl_xor_sync(~0u, sum, o2);
        float inv = 1.f / sum;
        pr[h * LT + lane] = e0 * inv;
        if (lane + 32 < LT) pr[h * LT + lane + 32] = e1 * inv;
        __syncwarp();
        float acc = 0.f;
        for (int j = 0; j <= step; j++) acc += pr[h * LT + j] * Vb[j * DM + lane];
        o[h * 32 + lane] = acc;
        __syncthreads();
        float val = __ldg(p.sbo + l * 256 + tid) + g_dx[b * DM + tid] +
                    dotk(o, p.swo + (size_t)l * 65536 + (size_t)tid * 256, 64);
        float mean = blksum(val, red) * (1.f / 256.f);
        float dd = val - mean;
        float var = blksum(dd * dd, red) * (1.f / 256.f);
        g_dx[b * DM + tid] = dd * rsqrtf(var + 1e-5f) * p.dlnw[l * 768 + tid] +
                             p.dlnb[l * 768 + tid];
      }
      gridbar();
      // C: crossQ + cross-attn + out-proj + resid + LN
      if (bid < BSZ) {
        int b = bid;
        float* x = SM;            // 256
        float* q = SM + 256;      // 256
        float* o = SM + 512;      // 256
        float* pr = SM + 768;     // 8*48
        float* red = SM + 1156;
        x[tid] = g_dx[b * DM + tid];
        __syncthreads();
        q[tid] = __ldg(p.cbqkv + l * 768 + tid) +
                 dotk(x, p.cwqkv + (size_t)l * 196608 + (size_t)tid * 256, 64);
        __syncthreads();
        int h = tid >> 5, lane = tid & 31;
        const float* Kb = g_cK + (size_t)l * ROWS_E * DM + (size_t)(b * SL) * DM + h * DHD;
        const float* Vb = g_cV + (size_t)l * ROWS_E * DM + (size_t)(b * SL) * DM + h * DHD;
        float s0 = 0.f, s1 = -1e30f;
#pragma unroll
        for (int d = 0; d < DHD; d++) s0 += q[h * 32 + d] * Kb[lane * DM + d];
        s0 *= scale;
        if (lane < SL - 32) {
          float a = 0.f;
#pragma unroll
          for (int d = 0; d < DHD; d++) a += q[h * 32 + d] * Kb[(lane + 32) * DM + d];
          s1 = a * scale;
        }
        float mx = fmaxf(s0, s1);
#pragma unroll
        for (int o2 = 16; o2; o2 >>= 1) mx = fmaxf(mx, __shfl_xor_sync(~0u, mx, o2));
        float e0 = expf(s0 - mx);
        float e1 = (lane < SL - 32) ? expf(s1 - mx) : 0.f;
        float sum = e0 + e1;
#pragma unroll
        for (int o2 = 16; o2; o2 >>= 1) sum += __shfl_xor_sync(~0u, sum, o2);
        float inv = 1.f / sum;
        pr[h * SL + lane] = e0 * inv;
        if (lane < SL - 32) pr[h * SL + lane + 32] = e1 * inv;
        __syncwarp();
        float acc = 0.f;
#pragma unroll 8
        for (int j = 0; j < SL; j++) acc += pr[h * SL + j] * Vb[j * DM + lane];
        o[h * 32 + lane] = acc;
        __syncthreads();
        float val = __ldg(p.cbo + l * 256 + tid) + g_dx[b * DM + tid] +
                    dotk(o, p.cwo + (size_t)l * 65536 + (size_t)tid * 256, 64);
        float mean = blksum(val, red) * (1.f / 256.f);
        float dd = val - mean;
        float var = blksum(dd * dd, red) * (1.f / 256.f);
        g_dx[b * DM + tid] = dd * rsqrtf(var + 1e-5f) * p.dlnw[l * 768 + 256 + tid] +
                             p.dlnb[l * 768 + 256 + tid];
      }
      gridbar();
      // D: FF1 (relu) -> g_dt[64x1024]
      for (int e = gtid; e < BSZ * FFD; e += GT) {
        int m = e >> 10, n = e & 1023;
        float v = __ldg(p.db1 + l * 1024 + n) +
                  dotk(g_dx + m * DM, p.dw1 + (size_t)l * 262144 + (size_t)n * 256, 64);
        g_dt[e] = fmaxf(v, 0.f);
      }
      gridbar();
      // E: FF2 + resid + LN  (+ final lnf at last layer)
      if (bid < BSZ) {
        int b = bid;
        float* hbuf = SM;           // 1024
        float* red = SM + 1024;
#pragma unroll
        for (int j = 0; j < 4; j++) hbuf[tid + 256 * j] = g_dt[b * FFD + tid + 256 * j];
        __syncthreads();
        float val = __ldg(p.db2 + l * 256 + tid) + g_dx[b * DM + tid] +
                    dotk(hbuf, p.dw2 + (size_t)l * 262144 + (size_t)tid * 1024, 256);
        float mean = blksum(val, red) * (1.f / 256.f);
        float dd = val - mean;
        float var = blksum(dd * dd, red) * (1.f / 256.f);
        float y = dd * rsqrtf(var + 1e-5f) * p.dlnw[l * 768 + 512 + tid] +
                  p.dlnb[l * 768 + 512 + tid];
        g_dx[b * DM + tid] = y;
        if (l == NLY - 1) {
          float m2 = blksum(y, red) * (1.f / 256.f);
          float d2 = y - m2;
          float v2 = blksum(d2 * d2, red) * (1.f / 256.f);
          g_dt2[b * DM + tid] = d2 * rsqrtf(v2 + 1e-5f) * p.lnfw[256 + tid] +
                                p.lnfb[256 + tid];
        }
      }
      gridbar();
    }
    // G: head GEMV + write logits + Gumbel-max sample + next token embed
    if (bid < BSZ) {
      int b = bid;
      float* hr = SM;             // 256
      float* lgs = SM + 256;      // 1024
      float* bv = SM + 1280;      // 256
      int* bxv = (int*)(SM + 1536);
      hr[tid] = g_dt2[b * DM + tid];
      __syncthreads();
      const float* hwp = p.hw + (size_t)step * VC * DM;
      float* outl = p.out + 3072 + ((size_t)step * BSZ + b) * VC;
#pragma unroll
      for (int j = 0; j < 4; j++) {
        int n = tid + 256 * j;
        float lv = __ldg(p.hb + step * VC + n) + dotk(hr, hwp + (size_t)n * 256, 64);
        outl[n] = lv;
        lgs[n] = lv;
      }
      __syncthreads();
      unsigned k0 = g_keys[2 * step], k1 = g_keys[2 * step + 1];
      const float tiny = 1.17549435e-38f;
      float best = -1e38f; int bi = 0;
#pragma unroll
      for (int j = 0; j < 4; j++) {
        int v = tid + 256 * j;
        uint2 r = tf2x32(k0, k1, 0u, (unsigned)(b * VC + v));
        unsigned bits = r.x ^ r.y;
        float f = __uint_as_float((bits >> 9) | 0x3f800000u) - 1.0f;
        float u = fmaxf(tiny, f + tiny);
        float g = -logf(-logf(u));
        float vv = g + __fdiv_rn(lgs[v], 0.1f);
        if (vv > best) { best = vv; bi = v; }
      }
      bv[tid] = best; bxv[tid] = bi;
      __syncthreads();
      for (int off = 128; off; off >>= 1) {
        if (tid < off) {
          float ov = bv[tid + off]; int oi = bxv[tid + off];
          if (ov > bv[tid] || (ov == bv[tid] && oi < bxv[tid])) {
            bv[tid] = ov; bxv[tid] = oi;
          }
        }
        __syncthreads();
      }
      int ch = bxv[0];
      if (tid == 0) g_choice[step * BSZ + b] = ch;
      if (step < SL - 1)
        g_dx[b * DM + tid] = p.emb[((size_t)step * VC + ch) * DM + tid] +
                             g_pe[(step + 1) * DM + tid];
    }
    gridbar();
  }

  // ---- final: s_cont [64,32] then s_cat [64,16] ----
  for (int e = gtid; e < BSZ * SL; e += GT) {
    if (e < 2048) {
      int b = e >> 5, s = e & 31;
      p.out[e] = (float)g_choice[s * BSZ + b];
    } else {
      int u = e - 2048, b = u >> 4, s = u & 15;
      p.out[e] = (float)g_choice[(32 + s) * BSZ + b];
    }
  }
}

extern "C" void kernel_launch(void* const* d_in, const int* in_sizes, int n_in,
                              void* d_out, int out_size) {
  Prm p;
  p.xc    = (const int*)  d_in[0];
  p.xcat  = (const int*)  d_in[1];
  p.sos   = (const float*)d_in[2];
  p.emb   = (const float*)d_in[3];
  p.hw    = (const float*)d_in[4];
  p.hb    = (const float*)d_in[5];
  p.ewqkv = (const float*)d_in[6];
  p.ebqkv = (const float*)d_in[7];
  p.ewo   = (const float*)d_in[8];
  p.ebo   = (const float*)d_in[9];
  p.ew1   = (const float*)d_in[10];
  p.eb1   = (const float*)d_in[11];
  p.ew2   = (const float*)d_in[12];
  p.eb2   = (const float*)d_in[13];
  p.elnw  = (const float*)d_in[14];
  p.elnb  = (const float*)d_in[15];
  p.swqkv = (const float*)d_in[16];
  p.sbqkv = (const float*)d_in[17];
  p.swo   = (const float*)d_in[18];
  p.sbo   = (const float*)d_in[19];
  p.cwqkv = (const float*)d_in[20];
  p.cbqkv = (const float*)d_in[21];
  p.cwo   = (const float*)d_in[22];
  p.cbo   = (const float*)d_in[23];
  p.dw1   = (const float*)d_in[24];
  p.db1   = (const float*)d_in[25];
  p.dw2   = (const float*)d_in[26];
  p.db2   = (const float*)d_in[27];
  p.dlnw  = (const float*)d_in[28];
  p.dlnb  = (const float*)d_in[29];
  p.lnfw  = (const float*)d_in[30];
  p.lnfb  = (const float*)d_in[31];
  p.out   = (float*)d_out;
  mega<<<NB, NT>>>(p);
}

// round 13
// speedup vs baseline: 1.5082x; 1.5082x over previous
#include <cuda_runtime.h>
#include <math.h>
#include <stdint.h>

#define NLY 6
#define DM 256
#define FFD 1024
#define VC 1024
#define SL 48
#define BSZ 64
#define NH 8
#define DHD 32
#define LT 49
#define ROWS_E (BSZ*SL)
#define NB 148
#define NT 256

// ---------------- device scratch ----------------
__device__ __align__(16) float g_pe[LT*DM];
__device__ unsigned g_keys[2*SL];
__device__ __align__(16) float g_X[ROWS_E*DM];
__device__ __align__(16) float g_T1[ROWS_E*FFD];
__device__ __align__(16) float g_T2[ROWS_E*DM];
__device__ __align__(16) float g_T3[ROWS_E*DM];
__device__ __align__(16) float g_mem[ROWS_E*DM];
__device__ __align__(16) float g_cK[NLY*ROWS_E*DM];
__device__ __align__(16) float g_cV[NLY*ROWS_E*DM];
__device__ __align__(16) float g_sK[NLY*BSZ*LT*DM];
__device__ __align__(16) float g_sV[NLY*BSZ*LT*DM];
__device__ unsigned g_barcnt = 0;
__device__ unsigned g_bargen = 0;

struct Prm {
  const int *xc, *xcat;
  const float *sos, *emb, *hw, *hb;
  const float *ewqkv, *ebqkv, *ewo, *ebo, *ew1, *eb1, *ew2, *eb2, *elnw, *elnb;
  const float *swqkv, *sbqkv, *swo, *sbo;
  const float *cwqkv, *cbqkv, *cwo, *cbo;
  const float *dw1, *db1, *dw2, *db2, *dlnw, *dlnb, *lnfw, *lnfb;
  float* out;
};

// ---------------- grid barrier (encoder phases only; 148 blocks) -----------
__device__ __forceinline__ void gridbar() {
  __threadfence();
  __syncthreads();
  if (threadIdx.x == 0) {
    unsigned gen = *(volatile unsigned*)&g_bargen;
    if (atomicAdd(&g_barcnt, 1u) == NB - 1u) {
      g_barcnt = 0u;
      __threadfence();
      atomicAdd(&g_bargen, 1u);
    } else {
      while (*(volatile unsigned*)&g_bargen == gen) __nanosleep(64);
    }
  }
  __syncthreads();
  __threadfence();   // gpu-scope => CCTL.IVALL: invalidate stale L1 lines
}

// ---------------- Threefry-2x32, 20 rounds ----------------
__device__ __forceinline__ uint2 tf2x32(unsigned k0, unsigned k1,
                                        unsigned x0, unsigned x1) {
  unsigned ks2 = k0 ^ k1 ^ 0x1BD11BDAu;
  x0 += k0; x1 += k1;
#define TFR(r) { x0 += x1; x1 = (x1 << (r)) | (x1 >> (32 - (r))); x1 ^= x0; }
  TFR(13) TFR(15) TFR(26) TFR(6)   x0 += k1;  x1 += ks2 + 1u;
  TFR(17) TFR(29) TFR(16) TFR(24)  x0 += ks2; x1 += k0 + 2u;
  TFR(13) TFR(15) TFR(26) TFR(6)   x0 += k0;  x1 += k1 + 3u;
  TFR(17) TFR(29) TFR(16) TFR(24)  x0 += k1;  x1 += ks2 + 4u;
  TFR(13) TFR(15) TFR(26) TFR(6)   x0 += ks2; x1 += k0 + 5u;
#undef TFR
  return make_uint2(x0, x1);
}

__device__ __forceinline__ float pef(int l, int d) {
  const float c = (float)(-9.210340371976184 / 256.0);
  float dv = expf((float)(2 * (d >> 1)) * c);
  float ang = (float)l * dv;
  return (d & 1) ? cosf(ang) : sinf(ang);
}

// ---------------- high-MLP GEMV dot helpers ----------------
// single dot, K=256
__device__ __forceinline__ float dot1(const float* xs, const float* w) {
  float s0 = 0.f, s1 = 0.f, s2 = 0.f, s3 = 0.f;
  const float4* x4 = (const float4*)xs;
  const float4* w4 = (const float4*)w;
#pragma unroll 16
  for (int i = 0; i < 64; i += 4) {
    float4 a0 = x4[i], b0 = __ldg(w4 + i);
    float4 a1 = x4[i+1], b1 = __ldg(w4 + i + 1);
    float4 a2 = x4[i+2], b2 = __ldg(w4 + i + 2);
    float4 a3 = x4[i+3], b3 = __ldg(w4 + i + 3);
    s0 = fmaf(a0.x,b0.x,fmaf(a0.y,b0.y,fmaf(a0.z,b0.z,fmaf(a0.w,b0.w,s0))));
    s1 = fmaf(a1.x,b1.x,fmaf(a1.y,b1.y,fmaf(a1.z,b1.z,fmaf(a1.w,b1.w,s1))));
    s2 = fmaf(a2.x,b2.x,fmaf(a2.y,b2.y,fmaf(a2.z,b2.z,fmaf(a2.w,b2.w,s2))));
    s3 = fmaf(a3.x,b3.x,fmaf(a3.y,b3.y,fmaf(a3.z,b3.z,fmaf(a3.w,b3.w,s3))));
  }
  return (s0 + s1) + (s2 + s3);
}

// 3 concurrent dots sharing x; weight rows at w, w+rs, w+2*rs (K=256)
__device__ __forceinline__ void dot3(const float* xs, const float* w, int rs,
                                     float& o0, float& o1, float& o2) {
  float s0 = 0.f, s1 = 0.f, s2 = 0.f;
  const float4* x4 = (const float4*)xs;
  const float4* w0 = (const float4*)w;
  const float4* w1 = (const float4*)(w + rs);
  const float4* w2 = (const float4*)(w + 2 * rs);
#pragma unroll 8
  for (int i = 0; i < 64; i++) {
    float4 a = x4[i];
    float4 b0 = __ldg(w0 + i), b1 = __ldg(w1 + i), b2 = __ldg(w2 + i);
    s0 = fmaf(a.x,b0.x,fmaf(a.y,b0.y,fmaf(a.z,b0.z,fmaf(a.w,b0.w,s0))));
    s1 = fmaf(a.x,b1.x,fmaf(a.y,b1.y,fmaf(a.z,b1.z,fmaf(a.w,b1.w,s1))));
    s2 = fmaf(a.x,b2.x,fmaf(a.y,b2.y,fmaf(a.z,b2.z,fmaf(a.w,b2.w,s2))));
  }
  o0 = s0; o1 = s1; o2 = s2;
}

// 4 concurrent dots sharing x; rows at w + j*rs (K=256)
__device__ __forceinline__ void dot4(const float* xs, const float* w, int rs,
                                     float& o0, float& o1, float& o2, float& o3) {
  float s0 = 0.f, s1 = 0.f, s2 = 0.f, s3 = 0.f;
  const float4* x4 = (const float4*)xs;
  const float4* w0 = (const float4*)w;
  const float4* w1 = (const float4*)(w + rs);
  const float4* w2 = (const float4*)(w + 2 * rs);
  const float4* w3 = (const float4*)(w + 3 * rs);
#pragma unroll 8
  for (int i = 0; i < 64; i++) {
    float4 a = x4[i];
    float4 b0 = __ldg(w0 + i), b1 = __ldg(w1 + i);
    float4 b2 = __ldg(w2 + i), b3 = __ldg(w3 + i);
    s0 = fmaf(a.x,b0.x,fmaf(a.y,b0.y,fmaf(a.z,b0.z,fmaf(a.w,b0.w,s0))));
    s1 = fmaf(a.x,b1.x,fmaf(a.y,b1.y,fmaf(a.z,b1.z,fmaf(a.w,b1.w,s1))));
    s2 = fmaf(a.x,b2.x,fmaf(a.y,b2.y,fmaf(a.z,b2.z,fmaf(a.w,b2.w,s2))));
    s3 = fmaf(a.x,b3.x,fmaf(a.y,b3.y,fmaf(a.z,b3.z,fmaf(a.w,b3.w,s3))));
  }
  o0 = s0; o1 = s1; o2 = s2; o3 = s3;
}

// single dot, K=1024
__device__ __forceinline__ float dot1k(const float* xs, const float* w) {
  float s0 = 0.f, s1 = 0.f, s2 = 0.f, s3 = 0.f;
  const float4* x4 = (const float4*)xs;
  const float4* w4 = (const float4*)w;
#pragma unroll 16
  for (int i = 0; i < 256; i += 4) {
    float4 a0 = x4[i], b0 = __ldg(w4 + i);
    float4 a1 = x4[i+1], b1 = __ldg(w4 + i + 1);
    float4 a2 = x4[i+2], b2 = __ldg(w4 + i + 2);
    float4 a3 = x4[i+3], b3 = __ldg(w4 + i + 3);
    s0 = fmaf(a0.x,b0.x,fmaf(a0.y,b0.y,fmaf(a0.z,b0.z,fmaf(a0.w,b0.w,s0))));
    s1 = fmaf(a1.x,b1.x,fmaf(a1.y,b1.y,fmaf(a1.z,b1.z,fmaf(a1.w,b1.w,s1))));
    s2 = fmaf(a2.x,b2.x,fmaf(a2.y,b2.y,fmaf(a2.z,b2.z,fmaf(a2.w,b2.w,s2))));
    s3 = fmaf(a3.x,b3.x,fmaf(a3.y,b3.y,fmaf(a3.z,b3.z,fmaf(a3.w,b3.w,s3))));
  }
  return (s0 + s1) + (s2 + s3);
}

// 32-float dot, both float4-aligned (smem q x global k-row)
__device__ __forceinline__ float dot32(const float* q, const float* k) {
  float s = 0.f;
  const float4* a = (const float4*)q;
  const float4* b = (const float4*)k;
#pragma unroll
  for (int i = 0; i < 8; i++) {
    float4 x = a[i], y = __ldg(b + i);
    s = fmaf(x.x,y.x,fmaf(x.y,y.y,fmaf(x.z,y.z,fmaf(x.w,y.w,s))));
  }
  return s;
}

// block-wide sum (256 threads)
__device__ __forceinline__ float blksum(float v, float* red) {
  int lane = threadIdx.x & 31, wp = threadIdx.x >> 5;
#pragma unroll
  for (int o = 16; o; o >>= 1) v += __shfl_xor_sync(0xffffffffu, v, o);
  if (lane == 0) red[wp] = v;
  __syncthreads();
  float t = 0.f;
#pragma unroll
  for (int i = 0; i < 8; i++) t += red[i];
  __syncthreads();
  return t;
}

// 64x64 tile of C = A(M,K)@B(N,K)^T + bias (+resid)(+relu)
__device__ __noinline__ void gtile(const float* A, const float* B,
                                   const float* bias, const float* resid,
                                   float* C, int N, int K, int relu,
                                   int bx, int by, float* SM) {
  float* As = SM;
  float* Bs = SM + 16 * 68;
  int t = threadIdx.x, tx = t & 15, ty = t >> 4;
  float acc[4][4] = {};
  const float* Ab = A + (size_t)(by * 64) * K;
  const float* Bb = B + (size_t)(bx * 64) * K;
  int lrow = t >> 2, lcol = (t & 3) * 4;
  for (int k0 = 0; k0 < K; k0 += 16) {
    float4 va = *(const float4*)(Ab + (size_t)lrow * K + k0 + lcol);
    As[(lcol + 0) * 68 + lrow] = va.x; As[(lcol + 1) * 68 + lrow] = va.y;
    As[(lcol + 2) * 68 + lrow] = va.z; As[(lcol + 3) * 68 + lrow] = va.w;
    float4 vb = *(const float4*)(Bb + (size_t)lrow * K + k0 + lcol);
    Bs[(lcol + 0) * 68 + lrow] = vb.x; Bs[(lcol + 1) * 68 + lrow] = vb.y;
    Bs[(lcol + 2) * 68 + lrow] = vb.z; Bs[(lcol + 3) * 68 + lrow] = vb.w;
    __syncthreads();
#pragma unroll
    for (int kk = 0; kk < 16; kk++) {
      float a[4], bb[4];
#pragma unroll
      for (int i = 0; i < 4; i++) a[i] = As[kk * 68 + ty * 4 + i];
#pragma unroll
      for (int j = 0; j < 4; j++) bb[j] = Bs[kk * 68 + tx * 4 + j];
#pragma unroll
      for (int i = 0; i < 4; i++)
#pragma unroll
        for (int j = 0; j < 4; j++) acc[i][j] = fmaf(a[i], bb[j], acc[i][j]);
    }
    __syncthreads();
  }
#pragma unroll
  for (int i = 0; i < 4; i++) {
    int m = by * 64 + ty * 4 + i;
#pragma unroll
    for (int j = 0; j < 4; j++) {
      int n = bx * 64 + tx * 4 + j;
      float v = acc[i][j];
      if (bias)  v += __ldg(bias + n);
      if (resid) v += resid[(size_t)m * N + n];
      if (relu)  v = fmaxf(v, 0.f);
      C[(size_t)m * N + n] = v;
    }
  }
  __syncthreads();
}

// encoder self-attn for one (head, batch); 256 threads
__device__ __noinline__ void enc_attn_unit(const float* QKV, float* O,
                                           int h, int b, float* SM) {
  float* Qs = SM;
  float* Ks = SM + 1536;
  float* Vs = SM + 3072;
  float* pr = SM + 4608;
  int t = threadIdx.x;
  for (int e = t; e < SL * DHD; e += NT) {
    int j = e >> 5, d = e & 31;
    const float* base = QKV + (size_t)(b * SL + j) * 768 + h * DHD + d;
    Qs[e] = base[0]; Ks[e] = base[256]; Vs[e] = base[512];
  }
  __syncthreads();
  int w = t >> 5, lane = t & 31;
  const float scale = 0.17677669529663687f;
  for (int q = w; q < SL; q += 8) {
    float s0 = 0.f, s1 = -1e30f;
#pragma unroll
    for (int d = 0; d < DHD; d++) s0 += Qs[q * 32 + d] * Ks[lane * 32 + d];
    s0 *= scale;
    if (lane < SL - 32) {
      float a = 0.f;
#pragma unroll
      for (int d = 0; d < DHD; d++) a += Qs[q * 32 + d] * Ks[(lane + 32) * 32 + d];
      s1 = a * scale;
    }
    float mx = fmaxf(s0, s1);
#pragma unroll
    for (int o = 16; o; o >>= 1) mx = fmaxf(mx, __shfl_xor_sync(~0u, mx, o));
    float e0 = expf(s0 - mx);
    float e1 = (lane < SL - 32) ? expf(s1 - mx) : 0.f;
    float sum = e0 + e1;
#pragma unroll
    for (int o = 16; o; o >>= 1) sum += __shfl_xor_sync(~0u, sum, o);
    float inv = 1.f / sum;
    pr[w * SL + lane] = e0 * inv;
    if (lane < SL - 32) pr[w * SL + lane + 32] = e1 * inv;
    __syncwarp();
    float acc = 0.f;
#pragma unroll 8
    for (int j = 0; j < SL; j++) acc += pr[w * SL + j] * Vs[j * 32 + lane];
    O[(size_t)(b * SL + q) * DM + h * DHD + lane] = acc;
    __syncwarp();
  }
  __syncthreads();
}

__device__ __forceinline__ void ln_rows(const float* x, const float* w,
                                        const float* b, float* out, int M,
                                        float* red) {
  int t = threadIdx.x;
  for (int r = blockIdx.x; r < M; r += NB) {
    float v = x[(size_t)r * DM + t];
    float mean = blksum(v, red) * (1.f / 256.f);
    float dd = v - mean;
    float var = blksum(dd * dd, red) * (1.f / 256.f);
    out[(size_t)r * DM + t] = dd * rsqrtf(var + 1e-5f) * w[t] + b[t];
  }
}

// ---------------- the megakernel ----------------
__global__ __launch_bounds__(NT, 1) void mega(Prm p) {
  __shared__ __align__(16) float SM[5248];
  const int bid = blockIdx.x, tid = threadIdx.x;
  const int gtid = bid * NT + tid;
  const int GT = NB * NT;
  const float scale = 0.17677669529663687f;

  // ---- init: pe, step keys, encoder embed ----
  for (int e = gtid; e < LT * DM; e += GT) g_pe[e] = pef(e >> 8, e & 255);
  if (gtid < SL) {
    uint2 r = tf2x32(0u, 42u, 0u, (unsigned)gtid);
    g_keys[2 * gtid] = r.x; g_keys[2 * gtid + 1] = r.y;
  }
  for (int e = gtid; e < ROWS_E * DM; e += GT) {
    int r = e >> 8, d = e & 255, b = r / SL, s = r % SL;
    int tok = (s < 32) ? p.xc[b * 32 + s] : p.xcat[b * 16 + (s - 32)];
    g_X[e] = p.emb[((size_t)s * VC + tok) * DM + d] + pef(s, d);
  }
  gridbar();

  // ---- encoder ----
  for (int l = 0; l < NLY; l++) {
    for (int t = bid; t < 576; t += NB)
      gtile(g_X, p.ewqkv + (size_t)l * 196608, p.ebqkv + l * 768, nullptr,
            g_T1, 768, 256, 0, t % 12, t / 12, SM);
    gridbar();
    for (int u = bid; u < NH * BSZ; u += NB)
      enc_attn_unit(g_T1, g_T2, u & 7, u >> 3, SM);
    gridbar();
    for (int t = bid; t < 192; t += NB)
      gtile(g_T2, p.ewo + (size_t)l * 65536, p.ebo + l * 256, g_X,
            g_T3, 256, 256, 0, t % 4, t / 4, SM);
    gridbar();
    ln_rows(g_T3, p.elnw + l * 512, p.elnb + l * 512, g_X, ROWS_E, SM);
    gridbar();
    for (int t = bid; t < 768; t += NB)
      gtile(g_X, p.ew1 + (size_t)l * 262144, p.eb1 + l * 1024, nullptr,
            g_T1, 1024, 256, 1, t % 16, t / 16, SM);
    gridbar();
    for (int t = bid; t < 192; t += NB)
      gtile(g_T1, p.ew2 + (size_t)l * 262144, p.eb2 + l * 256, g_X,
            g_T2, 256, 1024, 0, t % 4, t / 4, SM);
    gridbar();
    ln_rows(g_T2, p.elnw + l * 512 + 256, p.elnb + l * 512 + 256, g_X, ROWS_E, SM);
    gridbar();
  }
  ln_rows(g_X, p.lnfw, p.lnfb, g_mem, ROWS_E, SM);
  gridbar();

  // ---- cross-attn K/V precompute ----
  for (int t = bid; t < 2304; t += NB) {
    int l = t / 384, r = t % 384, kv = r / 192, tile = r % 192;
    const float* B = p.cwqkv + (size_t)l * 196608 + (size_t)(256 + kv * 256) * 256;
    const float* bias = p.cbqkv + l * 768 + 256 + kv * 256;
    float* C = (kv ? g_cV : g_cK) + (size_t)l * ROWS_E * DM;
    gtile(g_mem, B, bias, nullptr, C, 256, 256, 0, tile % 4, tile / 4, SM);
  }
  gridbar();   // last grid barrier — decode is per-batch independent

  if (bid >= BSZ) return;   // 84 blocks retire; 64 blocks decode independently

  // ---- fully in-block autoregressive decode for batch row b = bid ----
  const int b = bid;
  float* xb  = SM;                       // 256  current residual x
  float* qb  = SM + 256;                 // 256  q vector / lnf output
  float* ob  = SM + 512;                 // 256  attention output
  float* pr  = SM + 768;                 // 8*49 probs
  float* red = SM + 1160;                // 8
  float* hb  = SM + 1280;                // 1024 ff hidden / logits
  float* bv  = SM + 2304;                // 256  argmax values
  int*   bix = (int*)(SM + 2560);        // 256  argmax idx
  int*   chs = (int*)(SM + 2816);        // 48   chosen tokens
  const int h = tid >> 5, lane = tid & 31;

  xb[tid] = p.sos[tid] + g_pe[tid];
  __syncthreads();

  for (int step = 0; step < SL; step++) {
    for (int l = 0; l < NLY; l++) {
      float* Kc = g_sK + (size_t)(l * BSZ + b) * LT * DM;
      float* Vc = g_sV + (size_t)(l * BSZ + b) * LT * DM;
      // --- self-attn: fused qkv GEMV + cache append + attention + proj + LN
      {
        float qv, kv, vv;
        dot3(xb, p.swqkv + (size_t)l * 196608 + (size_t)tid * 256, 65536, qv, kv, vv);
        qb[tid] = qv + __ldg(p.sbqkv + l * 768 + tid);
        Kc[step * DM + tid] = kv + __ldg(p.sbqkv + l * 768 + 256 + tid);
        Vc[step * DM + tid] = vv + __ldg(p.sbqkv + l * 768 + 512 + tid);
        __syncthreads();
        const float* Kb = Kc + h * DHD;
        const float* Vb = Vc + h * DHD;
        float s0 = -1e30f, s1 = -1e30f;
        if (lane <= step)      s0 = dot32(qb + h * 32, Kb + lane * DM) * scale;
        if (lane + 32 <= step) s1 = dot32(qb + h * 32, Kb + (lane + 32) * DM) * scale;
        float mx = fmaxf(s0, s1);
#pragma unroll
        for (int o = 16; o; o >>= 1) mx = fmaxf(mx, __shfl_xor_sync(~0u, mx, o));
        float e0 = (lane <= step) ? expf(s0 - mx) : 0.f;
        float e1 = (lane + 32 <= step) ? expf(s1 - mx) : 0.f;
        float sum = e0 + e1;
#pragma unroll
        for (int o = 16; o; o >>= 1) sum += __shfl_xor_sync(~0u, sum, o);
        float inv = 1.f / sum;
        pr[h * LT + lane] = e0 * inv;
        if (lane + 32 < LT) pr[h * LT + lane + 32] = e1 * inv;
        __syncwarp();
        float acc = 0.f;
#pragma unroll 4
        for (int j = 0; j <= step; j++) acc += pr[h * LT + j] * Vb[j * DM + lane];
        ob[h * 32 + lane] = acc;
        __syncthreads();
        float val = __ldg(p.sbo + l * 256 + tid) + xb[tid] +
                    dot1(ob, p.swo + (size_t)l * 65536 + (size_t)tid * 256);
        float mean = blksum(val, red) * (1.f / 256.f);
        float dd = val - mean;
        float var = blksum(dd * dd, red) * (1.f / 256.f);
        xb[tid] = dd * rsqrtf(var + 1e-5f) * __ldg(p.dlnw + l * 768 + tid) +
                  __ldg(p.dlnb + l * 768 + tid);
        __syncthreads();
      }
      // --- cross-attn: Q GEMV + attention over cached memory K/V + proj + LN
      {
        qb[tid] = __ldg(p.cbqkv + l * 768 + tid) +
                  dot1(xb, p.cwqkv + (size_t)l * 196608 + (size_t)tid * 256);
        __syncthreads();
        const float* Kb = g_cK + ((size_t)l * ROWS_E + b * SL) * DM + h * DHD;
        const float* Vb = g_cV + ((size_t)l * ROWS_E + b * SL) * DM + h * DHD;
        float s0 = dot32(qb + h * 32, Kb + lane * DM) * scale;
        float s1 = (lane < SL - 32)
                   ? dot32(qb + h * 32, Kb + (lane + 32) * DM) * scale : -1e30f;
        float mx = fmaxf(s0, s1);
#pragma unroll
        for (int o = 16; o; o >>= 1) mx = fmaxf(mx, __shfl_xor_sync(~0u, mx, o));
        float e0 = expf(s0 - mx);
        float e1 = (lane < SL - 32) ? expf(s1 - mx) : 0.f;
        float sum = e0 + e1;
#pragma unroll
        for (int o = 16; o; o >>= 1) sum += __shfl_xor_sync(~0u, sum, o);
        float inv = 1.f / sum;
        pr[h * SL + lane] = e0 * inv;
        if (lane < SL - 32) pr[h * SL + lane + 32] = e1 * inv;
        __syncwarp();
        float acc = 0.f;
#pragma unroll 8
        for (int j = 0; j < SL; j++) acc += pr[h * SL + j] * Vb[j * DM + lane];
        ob[h * 32 + lane] = acc;
        __syncthreads();
        float val = __ldg(p.cbo + l * 256 + tid) + xb[tid] +
                    dot1(ob, p.cwo + (size_t)l * 65536 + (size_t)tid * 256);
        float mean = blksum(val, red) * (1.f / 256.f);
        float dd = val - mean;
        float var = blksum(dd * dd, red) * (1.f / 256.f);
        xb[tid] = dd * rsqrtf(var + 1e-5f) * __ldg(p.dlnw + l * 768 + 256 + tid) +
                  __ldg(p.dlnb + l * 768 + 256 + tid);
        __syncthreads();
      }
      // --- feed-forward: 4-way FF1 GEMV (relu) + FF2 dot-1024 + LN
      {
        float h0, h1, h2, h3;
        dot4(xb, p.dw1 + (size_t)l * 262144 + (size_t)tid * 256, 65536, h0, h1, h2, h3);
        hb[tid]       = fmaxf(h0 + __ldg(p.db1 + l * 1024 + tid), 0.f);
        hb[tid + 256] = fmaxf(h1 + __ldg(p.db1 + l * 1024 + tid + 256), 0.f);
        hb[tid + 512] = fmaxf(h2 + __ldg(p.db1 + l * 1024 + tid + 512), 0.f);
        hb[tid + 768] = fmaxf(h3 + __ldg(p.db1 + l * 1024 + tid + 768), 0.f);
        __syncthreads();
        float val = __ldg(p.db2 + l * 256 + tid) + xb[tid] +
                    dot1k(hb, p.dw2 + (size_t)l * 262144 + (size_t)tid * 1024);
        float mean = blksum(val, red) * (1.f / 256.f);
        float dd = val - mean;
        float var = blksum(dd * dd, red) * (1.f / 256.f);
        xb[tid] = dd * rsqrtf(var + 1e-5f) * __ldg(p.dlnw + l * 768 + 512 + tid) +
                  __ldg(p.dlnb + l * 768 + 512 + tid);
        __syncthreads();
      }
    }
    // --- final LN ---
    {
      float y = xb[tid];
      float mean = blksum(y, red) * (1.f / 256.f);
      float dd = y - mean;
      float var = blksum(dd * dd, red) * (1.f / 256.f);
      qb[tid] = dd * rsqrtf(var + 1e-5f) * __ldg(p.lnfw + 256 + tid) +
                __ldg(p.lnfb + 256 + tid);
      __syncthreads();
    }
    // --- head GEMV (4 logits/thread) + write logits + Gumbel-max sample ---
    {
      float l0, l1, l2, l3;
      dot4(qb, p.hw + ((size_t)step * VC + tid) * DM, 65536, l0, l1, l2, l3);
      float* outl = p.out + 3072 + ((size_t)step * BSZ + b) * VC;
      float lv;
      lv = l0 + __ldg(p.hb + step * VC + tid);        hb[tid] = lv;       outl[tid] = lv;
      lv = l1 + __ldg(p.hb + step * VC + tid + 256);  hb[tid + 256] = lv; outl[tid + 256] = lv;
      lv = l2 + __ldg(p.hb + step * VC + tid + 512);  hb[tid + 512] = lv; outl[tid + 512] = lv;
      lv = l3 + __ldg(p.hb + step * VC + tid + 768);  hb[tid + 768] = lv; outl[tid + 768] = lv;
      __syncthreads();
      unsigned k0 = g_keys[2 * step], k1 = g_keys[2 * step + 1];
      const float tiny = 1.17549435e-38f;
      float best = -1e38f; int bi = 0;
#pragma unroll
      for (int j = 0; j < 4; j++) {
        int v = tid + 256 * j;
        uint2 r = tf2x32(k0, k1, 0u, (unsigned)(b * VC + v));
        unsigned bits = r.x ^ r.y;
        float f = __uint_as_float((bits >> 9) | 0x3f800000u) - 1.0f;
        float u = fmaxf(tiny, f + tiny);
        float g = -logf(-logf(u));
        float vv = g + __fdiv_rn(hb[v], 0.1f);
        if (vv > best) { best = vv; bi = v; }
      }
      bv[tid] = best; bix[tid] = bi;
      __syncthreads();
      for (int off = 128; off; off >>= 1) {
        if (tid < off) {
          float ov = bv[tid + off]; int oi = bix[tid + off];
          if (ov > bv[tid] || (ov == bv[tid] && oi < bix[tid])) {
            bv[tid] = ov; bix[tid] = oi;
          }
        }
        __syncthreads();
      }
      int ch = bix[0];
      if (tid == 0) chs[step] = ch;
      if (step < SL - 1)
        xb[tid] = __ldg(p.emb + ((size_t)step * VC + ch) * DM + tid) +
                  g_pe[(step + 1) * DM + tid];
      __syncthreads();
    }
  }
  // ---- outputs: s_cont [64,32] then s_cat [64,16] (row-local) ----
  if (tid < 32)       p.out[b * 32 + tid] = (float)chs[tid];
  else if (tid < 48)  p.out[2048 + b * 16 + (tid - 32)] = (float)chs[tid];
}

extern "C" void kernel_launch(void* const* d_in, const int* in_sizes, int n_in,
                              void* d_out, int out_size) {
  Prm p;
  p.xc    = (const int*)  d_in[0];
  p.xcat  = (const int*)  d_in[1];
  p.sos   = (const float*)d_in[2];
  p.emb   = (const float*)d_in[3];
  p.hw    = (const float*)d_in[4];
  p.hb    = (const float*)d_in[5];
  p.ewqkv = (const float*)d_in[6];
  p.ebqkv = (const float*)d_in[7];
  p.ewo   = (const float*)d_in[8];
  p.ebo   = (const float*)d_in[9];
  p.ew1   = (const float*)d_in[10];
  p.eb1   = (const float*)d_in[11];
  p.ew2   = (const float*)d_in[12];
  p.eb2   = (const float*)d_in[13];
  p.elnw  = (const float*)d_in[14];
  p.elnb  = (const float*)d_in[15];
  p.swqkv = (const float*)d_in[16];
  p.sbqkv = (const float*)d_in[17];
  p.swo   = (const float*)d_in[18];
  p.sbo   = (const float*)d_in[19];
  p.cwqkv = (const float*)d_in[20];
  p.cbqkv = (const float*)d_in[21];
  p.cwo   = (const float*)d_in[22];
  p.cbo   = (const float*)d_in[23];
  p.dw1   = (const float*)d_in[24];
  p.db1   = (const float*)d_in[25];
  p.dw2   = (const float*)d_in[26];
  p.db2   = (const float*)d_in[27];
  p.dlnw  = (const float*)d_in[28];
  p.dlnb  = (const float*)d_in[29];
  p.lnfw  = (const float*)d_in[30];
  p.lnfb  = (const float*)d_in[31];
  p.out   = (float*)d_out;
  mega<<<NB, NT>>>(p);
}